// round 13
// baseline (speedup 1.0000x reference)
#include <cuda_runtime.h>
#include <cstdint>

// Problem constants
#define B_  2
#define T_  2048
#define D_  1024
#define H_  16
#define HD_ 64
#define M_  (B_ * T_)      // 4096

// tcgen05 is sm_103a-SPECIFIC; the harness also compiles a compute_103 pass.
#if defined(__CUDA_ARCH__) && (__CUDA_ARCH__ >= 1000) && defined(__CUDA_ARCH_FEAT_SM103_ALL)
#define HAS_TCGEN05 1
#else
#define HAS_TCGEN05 0
#endif

// Scratch (device globals: allocation-free per harness rules)
__device__ float g_Q[B_ * H_ * T_ * HD_];   // holds Q * 0.125 (exact 2^-3 scale)
__device__ float g_K[B_ * H_ * T_ * HD_];
__device__ float g_V[B_ * H_ * T_ * HD_];
__device__ float g_S[B_ * T_ * D_];
// tf32-pre-rounded copies of the GEMM inputs
__device__ float g_x [M_ * D_];
__device__ float g_W1[3 * D_ * D_];
__device__ float g_W2[D_ * D_];

// ---------------------------------------------------------------------------
// Helpers available on all passes
// ---------------------------------------------------------------------------
__device__ __forceinline__ uint32_t f2tf32(float x) {
    uint32_t u;
    asm("cvt.rna.tf32.f32 %0, %1;" : "=r"(u) : "f"(x));
    return u;
}
__device__ __forceinline__ float rnd_tf32(float x) {
    return __uint_as_float(f2tf32(x));
}
__device__ __forceinline__ uint32_t smem_u32(const void* p) {
    uint32_t a;
    asm("{ .reg .u64 t; cvta.to.shared.u64 t, %1; cvt.u32.u64 %0, t; }"
        : "=r"(a) : "l"(p));
    return a;
}
#define SW128(o) ((o) ^ (((o) >> 3) & 0x70))

#define CP_ASYNC16(dst, src) \
    asm volatile("cp.async.cg.shared.global [%0], [%1], 16;" \
                 :: "r"((uint32_t)(dst)), "l"(src))
#define CP_COMMIT() asm volatile("cp.async.commit_group;" ::: "memory")
#define CP_WAIT(n)  asm volatile("cp.async.wait_group %0;" :: "n"(n) : "memory")

#define MBARRIER_INIT(mb, cnt) \
    asm volatile("mbarrier.init.shared.b64 [%0], %1;" \
                 :: "r"((uint32_t)(mb)), "r"((uint32_t)(cnt)) : "memory")

#define MBARRIER_WAIT_PARITY(mb, par) do {                                        \
    uint32_t _m = (uint32_t)(mb);                                                 \
    uint32_t _p = (uint32_t)(par);                                                \
    uint32_t _done;                                                               \
    asm volatile(                                                                 \
        "{\n\t.reg .pred p;\n\t"                                                  \
        "mbarrier.try_wait.parity.acquire.cta.shared::cta.b64 p, [%1], %2;\n\t"   \
        "selp.b32 %0, 1, 0, p;\n\t}"                                              \
        : "=r"(_done) : "r"(_m), "r"(_p) : "memory");                             \
    if (!_done) {                                                                 \
        asm volatile(                                                             \
            "{\n\t.reg .pred P1;\n\t"                                             \
            "WL_%=:\n\t"                                                          \
            "mbarrier.try_wait.parity.acquire.cta.shared::cta.b64 P1, [%0], %1, 0x989680;\n\t" \
            "@P1 bra.uni WD_%=;\n\t"                                              \
            "bra.uni WL_%=;\n\t"                                                  \
            "WD_%=:\n\t}"                                                         \
            :: "r"(_m), "r"(_p) : "memory");                                      \
    }                                                                             \
} while (0)

#define FENCE_ASYNC_SHARED() asm volatile("fence.proxy.async.shared::cta;" ::: "memory")

#if HAS_TCGEN05
// ---------------------------------------------------------------------------
// tcgen05 helpers (sm_103a only)
// ---------------------------------------------------------------------------
__device__ __forceinline__ uint32_t elect_one() {
    uint32_t p;
    asm volatile("{ .reg .pred p; elect.sync _|p, 0xFFFFFFFF; selp.b32 %0, 1, 0, p; }"
                 : "=r"(p));
    return p;
}
__device__ __forceinline__ uint64_t mk_desc(uint32_t saddr) {
    const uint64_t base = (2ull << 61) | (1ull << 46) | (64ull << 32) | (1ull << 16);
    return base | ((uint64_t)(saddr >> 4) & 0x3FFF);
}

#define IDESC_TF32_N256 ((1u << 4) | (2u << 7) | (2u << 10) | (32u << 17) | (8u << 24))
#define IDESC_TF32_N128 ((1u << 4) | (2u << 7) | (2u << 10) | (16u << 17) | (8u << 24))
#define IDESC_TF32_N64  ((1u << 4) | (2u << 7) | (2u << 10) | ( 8u << 17) | (8u << 24))

__device__ __forceinline__ void mma_tf32_ss(uint32_t d, uint64_t ad, uint64_t bd,
                                            uint32_t idesc, bool en) {
    uint32_t e = en ? 1u : 0u;
    asm volatile(
        "{\n\t.reg .pred p;\n\tsetp.ne.u32 p, %5, 0;\n\t"
        "tcgen05.mma.cta_group::1.kind::tf32 [%0], %1, %2, %3, {%4, %4, %4, %4}, p;\n\t}"
        :: "r"(d), "l"(ad), "l"(bd), "r"(idesc), "r"(0u), "r"(e) : "memory");
}
__device__ __forceinline__ void mma_tf32_ts(uint32_t d, uint32_t a_tm, uint64_t bd,
                                            uint32_t idesc, bool en) {
    uint32_t e = en ? 1u : 0u;
    asm volatile(
        "{\n\t.reg .pred p;\n\tsetp.ne.u32 p, %5, 0;\n\t"
        "tcgen05.mma.cta_group::1.kind::tf32 [%0], [%1], %2, %3, {%4, %4, %4, %4}, p;\n\t}"
        :: "r"(d), "r"(a_tm), "l"(bd), "r"(idesc), "r"(0u), "r"(e) : "memory");
}

#define TCGEN05_ALLOC(smem_res, n) \
    asm volatile("tcgen05.alloc.cta_group::1.sync.aligned.shared::cta.b32 [%0], %1;" \
                 :: "r"((uint32_t)(smem_res)), "r"((uint32_t)(n)) : "memory")
#define TCGEN05_DEALLOC(tm, n) \
    asm volatile("tcgen05.dealloc.cta_group::1.sync.aligned.b32 %0, %1;" \
                 :: "r"(tm), "r"((uint32_t)(n)))
#define TCGEN05_RELINQ() \
    asm volatile("tcgen05.relinquish_alloc_permit.cta_group::1.sync.aligned;")
#define TCGEN05_COMMIT(mb) \
    asm volatile("tcgen05.commit.cta_group::1.mbarrier::arrive::one.shared::cluster.b64 [%0];" \
                 :: "r"((uint32_t)(mb)) : "memory")
#define TCGEN05_FENCE_BEFORE() asm volatile("tcgen05.fence::before_thread_sync;" ::: "memory")
#define TCGEN05_FENCE_AFTER()  asm volatile("tcgen05.fence::after_thread_sync;" ::: "memory")
#define TCGEN05_WAIT_LD() asm volatile("tcgen05.wait::ld.sync.aligned;" ::: "memory")
#define TCGEN05_WAIT_ST() asm volatile("tcgen05.wait::st.sync.aligned;" ::: "memory")

#define TCGEN05_LD_X32(r, ta) \
    asm volatile( \
        "tcgen05.ld.sync.aligned.32x32b.x32.b32 " \
        "{%0, %1, %2, %3, %4, %5, %6, %7, %8, %9, %10, %11, %12, %13, %14, %15, " \
        " %16, %17, %18, %19, %20, %21, %22, %23, %24, %25, %26, %27, %28, %29, %30, %31}, [%32];" \
        : "=r"((r)[0]),  "=r"((r)[1]),  "=r"((r)[2]),  "=r"((r)[3]), \
          "=r"((r)[4]),  "=r"((r)[5]),  "=r"((r)[6]),  "=r"((r)[7]), \
          "=r"((r)[8]),  "=r"((r)[9]),  "=r"((r)[10]), "=r"((r)[11]), \
          "=r"((r)[12]), "=r"((r)[13]), "=r"((r)[14]), "=r"((r)[15]), \
          "=r"((r)[16]), "=r"((r)[17]), "=r"((r)[18]), "=r"((r)[19]), \
          "=r"((r)[20]), "=r"((r)[21]), "=r"((r)[22]), "=r"((r)[23]), \
          "=r"((r)[24]), "=r"((r)[25]), "=r"((r)[26]), "=r"((r)[27]), \
          "=r"((r)[28]), "=r"((r)[29]), "=r"((r)[30]), "=r"((r)[31]) \
        : "r"(ta))

#define TCGEN05_ST_X32(ta, r) \
    asm volatile( \
        "tcgen05.st.sync.aligned.32x32b.x32.b32 [%0], " \
        "{%1, %2, %3, %4, %5, %6, %7, %8, %9, %10, %11, %12, %13, %14, %15, %16, " \
        " %17, %18, %19, %20, %21, %22, %23, %24, %25, %26, %27, %28, %29, %30, %31, %32};" \
        :: "r"(ta), \
           "r"((r)[0]),  "r"((r)[1]),  "r"((r)[2]),  "r"((r)[3]), \
           "r"((r)[4]),  "r"((r)[5]),  "r"((r)[6]),  "r"((r)[7]), \
           "r"((r)[8]),  "r"((r)[9]),  "r"((r)[10]), "r"((r)[11]), \
           "r"((r)[12]), "r"((r)[13]), "r"((r)[14]), "r"((r)[15]), \
           "r"((r)[16]), "r"((r)[17]), "r"((r)[18]), "r"((r)[19]), \
           "r"((r)[20]), "r"((r)[21]), "r"((r)[22]), "r"((r)[23]), \
           "r"((r)[24]), "r"((r)[25]), "r"((r)[26]), "r"((r)[27]), \
           "r"((r)[28]), "r"((r)[29]), "r"((r)[30]), "r"((r)[31]) \
        : "memory")
#endif  // HAS_TCGEN05

// ---------------------------------------------------------------------------
// Kernel 0: pre-round x, Wqkv, Wproj to tf32 (rna) into device-global copies.
// ---------------------------------------------------------------------------
#define NX4  1048576
#define NW14  786432
#define NW24  262144
#define NTOT (NX4 + NW14 + NW24)

__global__ void cvt_tf32_kernel(const float* __restrict__ x,
                                const float* __restrict__ w1,
                                const float* __restrict__ w2)
{
    const int stride = gridDim.x * blockDim.x;
    for (int i = blockIdx.x * blockDim.x + threadIdx.x; i < NTOT; i += stride) {
        const float4* s; float4* d; int off;
        if (i < NX4)              { s = (const float4*)x;  d = (float4*)g_x;  off = i; }
        else if (i < NX4 + NW14)  { s = (const float4*)w1; d = (float4*)g_W1; off = i - NX4; }
        else                      { s = (const float4*)w2; d = (float4*)g_W2; off = i - NX4 - NW14; }
        float4 v = s[off];
        v.x = rnd_tf32(v.x); v.y = rnd_tf32(v.y);
        v.z = rnd_tf32(v.z); v.w = rnd_tf32(v.w);
        d[off] = v;
    }
}

// ---------------------------------------------------------------------------
// qkv GEMM — R13: C[256m x 256n] per CTA. Two M=128 MMAs share one W stage
// (halves W L2 traffic: 576 -> 384 MB; grid 384 -> 192 CTAs).
// 3 stages x 64KB, R9-proven ordering (gate -> issue kt+2 -> CP_WAIT(2)).
// ---------------------------------------------------------------------------
#define QST 65536u   // stage: A 32KB (2 x 16KB chunks) + W 32KB

__global__ __launch_bounds__(256)
void tc_gemm_qkv(const float* __restrict__ bias)
{
#if HAS_TCGEN05
    extern __shared__ uint8_t dsm_raw[];
    uint8_t* dsm = (uint8_t*)((((uintptr_t)dsm_raw) + 1023) & ~(uintptr_t)1023);

    __shared__ uint32_t s_tmem;
    __shared__ __align__(8) unsigned long long s_mbar[3];

    const int tid  = threadIdx.x;
    const int wid  = tid >> 5;
    const int lane = tid & 31;
    const int m0 = blockIdx.y * 256, n0 = blockIdx.x * 256;
    const uint32_t sb = smem_u32(dsm);

    if (wid == 0) { TCGEN05_ALLOC(smem_u32(&s_tmem), 512); TCGEN05_RELINQ(); }
    if (tid == 0)
#pragma unroll
        for (int j = 0; j < 3; j++) MBARRIER_INIT(smem_u32(&s_mbar[j]), 1);
    __syncthreads();
    const uint32_t tmem = s_tmem;
    uint32_t mb[3];
#pragma unroll
    for (int j = 0; j < 3; j++) mb[j] = smem_u32(&s_mbar[j]);

    const int row = tid >> 3;     // 0..31 (+32 per group)
    const int q   = tid & 7;
    const char* Ag = (const char*)(g_x  + (size_t)(m0 + row) * 1024 + q * 4);
    const char* Wg = (const char*)(g_W1 + (size_t)(n0 + row) * 1024 + q * 4);

    const uint32_t doff = SW128((uint32_t)row * 128u + (uint32_t)q * 16u);
    // SW128 permutes only bits [6:4]^[9:7]; +i*4096 (bit 12+) commutes.
    // A spans 256 rows = 8 groups of 32; groups 4..7 land in chunk 1 at
    // +16384 = doff + 4096*i continuing seamlessly.

    auto issue_stage = [&](int kt, int st) {
        const uint32_t base = sb + (uint32_t)st * QST;
        const char* a = Ag + (size_t)kt * 128;
        const char* w = Wg + (size_t)kt * 128;
#pragma unroll
        for (int i = 0; i < 8; i++)
            CP_ASYNC16(base + doff + 4096u * i, a + (size_t)i * 131072);
#pragma unroll
        for (int i = 0; i < 8; i++)
            CP_ASYNC16(base + 32768u + doff + 4096u * i, w + (size_t)i * 131072);
    };

    issue_stage(0, 0); CP_COMMIT();
    issue_stage(1, 1); CP_COMMIT();

    for (int kt = 0; kt < 32; kt++) {
        if (kt + 2 < 32) {
            // stage (kt+2)%3 last used by MMA(kt-1): distance-1 gate, hidden
            // under the doubled (1024-cyc) per-ktile MMA work
            const int g = kt - 1;
            if (g >= 0) MBARRIER_WAIT_PARITY(mb[g % 3], ((g / 3) & 1));
            issue_stage(kt + 2, (kt + 2) % 3); CP_COMMIT();
            CP_WAIT(2);          // stage kt landed, 3 groups deep
        } else if (kt == 30) {
            CP_WAIT(1);
        } else {
            CP_WAIT(0);
        }
        __syncthreads();
        FENCE_ASYNC_SHARED();
        if (wid == 0 && elect_one()) {
            const uint32_t base = sb + (uint32_t)(kt % 3) * QST;
            uint64_t bd = mk_desc(base + 32768u);
#pragma unroll
            for (int mi = 0; mi < 2; mi++) {
                uint64_t ad = mk_desc(base + (uint32_t)mi * 16384u);
#pragma unroll
                for (int s = 0; s < 4; s++)
                    mma_tf32_ss(tmem + mi * 256, ad + s * 2, bd + s * 2,
                                IDESC_TF32_N256, (kt > 0) || (s > 0));
            }
            TCGEN05_COMMIT(mb[kt % 3]);
        }
    }
    // drain: slot j last fired at kt = j + ((31-j)/3)*3 -> parity (last/3)&1
#pragma unroll
    for (int j = 0; j < 3; j++) {
        const int last = j + ((31 - j) / 3) * 3;
        MBARRIER_WAIT_PARITY(mb[j], (last / 3) & 1);
    }
    TCGEN05_FENCE_AFTER();

    // Epilogue: TMEM -> smem transpose (pad 33) -> QKV scatter
    float* dch = (float*)dsm;
#pragma unroll 1
    for (int mi = 0; mi < 2; mi++) {
        for (int c = 0; c < 8; c++) {
            __syncthreads();
            if (wid < 4) {
                uint32_t r[32];
                TCGEN05_LD_X32(r, tmem + mi * 256 + c * 32);
                TCGEN05_WAIT_LD();
                const int rr = wid * 32 + lane;
#pragma unroll
                for (int j = 0; j < 32; j++) dch[rr * 33 + j] = __uint_as_float(r[j]);
            }
            __syncthreads();
#pragma unroll
            for (int i = 0; i < 4; i++) {
                const int rr = (tid >> 3) + 32 * i;
                const int qq = tid & 7;
                const int n  = n0 + c * 32 + qq * 4;
                float4 bb = *(const float4*)&bias[n];
                float4 o;
                o.x = dch[rr * 33 + qq * 4 + 0] + bb.x;
                o.y = dch[rr * 33 + qq * 4 + 1] + bb.y;
                o.z = dch[rr * 33 + qq * 4 + 2] + bb.z;
                o.w = dch[rr * 33 + qq * 4 + 3] + bb.w;
                const int m = m0 + mi * 128 + rr;
                const int which = n >> 10;
                const float sc = (which == 0) ? 0.125f : 1.0f;   // exact 2^-3
                o.x = rnd_tf32(o.x * sc); o.y = rnd_tf32(o.y * sc);
                o.z = rnd_tf32(o.z * sc); o.w = rnd_tf32(o.w * sc);
                const int b = m >> 11, t = m & 2047;
                const int dn = n & 1023, h = dn >> 6, hd = dn & 63;
                float* dst = (which == 0) ? g_Q : ((which == 1) ? g_K : g_V);
                *(float4*)&dst[((size_t)(b * H_ + h) * T_ + t) * HD_ + hd] = o;
            }
        }
    }
    __syncthreads();
    if (wid == 0) TCGEN05_DEALLOC(tmem, 512);

#else  // ------- naive fallback (non-'a' compile pass; never selected) -------
    const int tid = threadIdx.x;
    const int m0 = blockIdx.y * 256, n0 = blockIdx.x * 256;
    for (int idx = tid; idx < 256 * 256; idx += 256) {
        int m = m0 + (idx >> 8);
        int n = n0 + (idx & 255);
        float acc = bias[n];
        for (int k = 0; k < 1024; k++)
            acc += g_x[(size_t)m * 1024 + k] * g_W1[(size_t)n * 1024 + k];
        int b = m >> 11, t = m & 2047;
        int which = n >> 10, dn = n & 1023, h = dn >> 6, hd = dn & 63;
        if (which == 0) acc *= 0.125f;
        float* dst = (which == 0) ? g_Q : ((which == 1) ? g_K : g_V);
        dst[((size_t)(b * H_ + h) * T_ + t) * HD_ + hd] = acc;
    }
#endif
}

// ---------------------------------------------------------------------------
// proj GEMM (R9-proven): C[128m x 256n] per CTA, 4-stage cp.async pipeline,
// stage-reuse distance 2, depth-3 prefetch.
// ---------------------------------------------------------------------------
#define GST 49152u

__global__ __launch_bounds__(256)
void tc_gemm_proj(const float* __restrict__ bias, float* __restrict__ out)
{
#if HAS_TCGEN05
    extern __shared__ uint8_t dsm_raw[];
    uint8_t* dsm = (uint8_t*)((((uintptr_t)dsm_raw) + 1023) & ~(uintptr_t)1023);

    __shared__ uint32_t s_tmem;
    __shared__ __align__(8) unsigned long long s_mbar[4];

    const int tid  = threadIdx.x;
    const int wid  = tid >> 5;
    const int lane = tid & 31;
    const int m0 = blockIdx.y * 128, n0 = blockIdx.x * 256;
    const uint32_t sb = smem_u32(dsm);

    if (wid == 0) { TCGEN05_ALLOC(smem_u32(&s_tmem), 256); TCGEN05_RELINQ(); }
    if (tid == 0)
#pragma unroll
        for (int j = 0; j < 4; j++) MBARRIER_INIT(smem_u32(&s_mbar[j]), 1);
    __syncthreads();
    const uint32_t tmem = s_tmem;
    uint32_t mb[4];
#pragma unroll
    for (int j = 0; j < 4; j++) mb[j] = smem_u32(&s_mbar[j]);

    const int row = tid >> 3;
    const int q   = tid & 7;
    const char* Ag = (const char*)(g_S  + (size_t)(m0 + row) * 1024 + q * 4);
    const char* Wg = (const char*)(g_W2 + (size_t)(n0 + row) * 1024 + q * 4);

    const uint32_t doff = SW128((uint32_t)row * 128u + (uint32_t)q * 16u);

    auto issue_stage = [&](int kt, int st) {
        const uint32_t base = sb + (uint32_t)st * GST;
        const char* a = Ag + (size_t)kt * 128;
        const char* w = Wg + (size_t)kt * 128;
#pragma unroll
        for (int i = 0; i < 4; i++)
            CP_ASYNC16(base + ((doff + 4096u * i) & 0x7FFFu), a + (size_t)i * 131072);
#pragma unroll
        for (int i = 0; i < 8; i++)
            CP_ASYNC16(base + 16384u + ((doff + 4096u * i) & 0xFFFFu), w + (size_t)i * 131072);
    };

    issue_stage(0, 0); CP_COMMIT();
    issue_stage(1, 1); CP_COMMIT();

    for (int kt = 0; kt < 32; kt++) {
        if (kt + 2 < 32) {
            if (kt >= 2)
                MBARRIER_WAIT_PARITY(mb[(kt - 2) & 3], ((kt - 2) >> 2) & 1);
            issue_stage(kt + 2, (kt + 2) & 3); CP_COMMIT();
            CP_WAIT(2);
        } else if (kt == 30) {
            CP_WAIT(1);
        } else {
            CP_WAIT(0);
        }
        __syncthreads();
        FENCE_ASYNC_SHARED();
        if (wid == 0 && elect_one()) {
            const uint32_t base = sb + (uint32_t)(kt & 3) * GST;
            uint64_t ad = mk_desc(base), bd = mk_desc(base + 16384u);
#pragma unroll
            for (int s = 0; s < 4; s++)
                mma_tf32_ss(tmem, ad + s * 2, bd + s * 2, IDESC_TF32_N256,
                            (kt > 0) || (s > 0));
            TCGEN05_COMMIT(mb[kt & 3]);
        }
    }
#pragma unroll
    for (int j = 0; j < 4; j++) MBARRIER_WAIT_PARITY(mb[j], 1);
    TCGEN05_FENCE_AFTER();

    float* dch = (float*)dsm;
    for (int c = 0; c < 8; c++) {
        __syncthreads();
        if (wid < 4) {
            uint32_t r[32];
            TCGEN05_LD_X32(r, tmem + c * 32);
            TCGEN05_WAIT_LD();
            const int rr = wid * 32 + lane;
#pragma unroll
            for (int j = 0; j < 32; j++) dch[rr * 33 + j] = __uint_as_float(r[j]);
        }
        __syncthreads();
#pragma unroll
        for (int i = 0; i < 4; i++) {
            const int rr = (tid >> 3) + 32 * i;
            const int qq = tid & 7;
            const int n  = n0 + c * 32 + qq * 4;
            float4 bb = *(const float4*)&bias[n];
            float4 o;
            o.x = dch[rr * 33 + qq * 4 + 0] + bb.x;
            o.y = dch[rr * 33 + qq * 4 + 1] + bb.y;
            o.z = dch[rr * 33 + qq * 4 + 2] + bb.z;
            o.w = dch[rr * 33 + qq * 4 + 3] + bb.w;
            const int m = m0 + rr;
            *(float4*)&out[(size_t)m * D_ + n] = o;
        }
    }
    __syncthreads();
    if (wid == 0) TCGEN05_DEALLOC(tmem, 256);

#else  // ------- naive fallback (non-'a' compile pass; never selected) -------
    const int tid = threadIdx.x;
    const int m0 = blockIdx.y * 128, n0 = blockIdx.x * 256;
    for (int idx = tid; idx < 128 * 256; idx += 256) {
        int m = m0 + (idx >> 8);
        int n = n0 + (idx & 255);
        float acc = bias[n];
        for (int k = 0; k < 1024; k++)
            acc += g_S[(size_t)m * 1024 + k] * g_W2[(size_t)n * 1024 + k];
        out[(size_t)m * D_ + n] = acc;
    }
#endif
}

// ---------------------------------------------------------------------------
// tcgen05 causal flash attention (exact R9 config). BR=BC=128, HD=64,
// grid (16, 32), 512 thr; warp (w&3, w>>2) owns one LDTM.x32 + 32 exps +
// one STTM.x32 per iter. TMEM: S0@0, S1@128, P@256, O@384.
// ---------------------------------------------------------------------------
#define FA_QOFF 0u
#define FA_KOFF 32768u
#define FA_VOFF 98304u
#define FA_DSM  163840
#define FA_THREADS 512

__global__ __launch_bounds__(FA_THREADS)
void flash_tc()
{
#if HAS_TCGEN05
    extern __shared__ uint8_t dsm_raw[];
    uint8_t* dsm = (uint8_t*)((((uintptr_t)dsm_raw) + 1023) & ~(uintptr_t)1023);

    __shared__ uint32_t s_tmem;
    __shared__ __align__(8) unsigned long long s_mbar_s, s_mbar_o;
    __shared__ float s_rows[4][128];

    const int tid  = threadIdx.x;
    const int wid  = tid >> 5;
    const int lane = tid & 31;
    const int qb   = (int)(gridDim.x - 1 - blockIdx.x);   // heavy tiles first
    const int bh   = blockIdx.y;

    const int rg  = wid & 3;
    const int q4  = wid >> 2;
    const int row = (rg << 5) + lane;
    const uint32_t wo = (uint32_t)rg << 21;

    const uint32_t sb = smem_u32(dsm);
    if (wid == 0) { TCGEN05_ALLOC(smem_u32(&s_tmem), 512); TCGEN05_RELINQ(); }
    if (tid == 0) { MBARRIER_INIT(smem_u32(&s_mbar_s), 1); MBARRIER_INIT(smem_u32(&s_mbar_o), 1); }
    __syncthreads();
    const uint32_t tmem = s_tmem;
    const uint32_t mbs = smem_u32(&s_mbar_s), mbo = smem_u32(&s_mbar_o);

    const int lr0 = tid >> 4;
    const int ld4 = (tid & 15) << 2;
    const int lcj = ld4 >> 5, lkk = ld4 & 31;
    const uint32_t ldst = (uint32_t)lcj * 16384u + SW128((uint32_t)lr0 * 128u + (uint32_t)lkk * 4u);

    auto cp_tile = [&](const float* Gg, uint32_t smoff) {
#pragma unroll
        for (int it = 0; it < 4; it++)
            CP_ASYNC16(sb + smoff + ((ldst + 4096u * it) & 0x7FFFu),
                       (const char*)(Gg + (size_t)(lr0 + 32 * it) * 64 + ld4));
    };

    const float* Qg = g_Q + ((size_t)bh * T_ + (size_t)qb * 128) * HD_;

    const int vrb = tid >> 4, vdb = tid & 15;

    auto issue_smma = [&](int kbuf, int sbuf) {
        const uint32_t kbase = sb + FA_KOFF + (uint32_t)kbuf * 32768u;
#pragma unroll
        for (int cj = 0; cj < 2; cj++) {
            uint64_t ad = mk_desc(sb + FA_QOFF + cj * 16384);
            uint64_t bd = mk_desc(kbase + cj * 16384);
#pragma unroll
            for (int s = 0; s < 4; s++)
                mma_tf32_ss(tmem + sbuf * 128, ad + s * 2, bd + s * 2,
                            IDESC_TF32_N128, (cj > 0) || (s > 0));
        }
    };

    auto v_ldg = [&](int kb, float4* vreg) {
        const float* Vg = g_V + ((size_t)bh * T_ + (size_t)kb * 128) * HD_;
        const int r0 = vrb * 4, d0 = vdb * 4;
#pragma unroll
        for (int m = 0; m < 4; m++)
            vreg[m] = *(const float4*)&Vg[(r0 + m) * 64 + d0];
    };
    auto v_sts = [&](int b, const float4* vreg) {
        const uint32_t vbase = FA_VOFF + (uint32_t)b * 32768u;
        const int r0 = vrb * 4, d0 = vdb * 4;
        const int vj = r0 >> 5, kk0 = r0 & 31;
#pragma unroll
        for (int m = 0; m < 4; m++) {
            float4 u;
            u.x = ((const float*)&vreg[0])[m];
            u.y = ((const float*)&vreg[1])[m];
            u.z = ((const float*)&vreg[2])[m];
            u.w = ((const float*)&vreg[3])[m];
            uint32_t off = (uint32_t)(d0 + m) * 128u + (uint32_t)kk0 * 4u;
            *(float4*)(dsm + vbase + vj * 8192 + SW128(off)) = u;
        }
    };

    // ---- prologue ----
    cp_tile(Qg, FA_QOFF);
    cp_tile(g_K + ((size_t)bh * T_ + 0) * HD_, FA_KOFF);
    CP_COMMIT();
    if (qb > 0) {
        cp_tile(g_K + ((size_t)bh * T_ + 128) * HD_, FA_KOFF + 32768u);
        CP_COMMIT();
    }
    {
        float4 v0[4];
        v_ldg(0, v0);
        v_sts(0, v0);
    }
    if (qb > 0) CP_WAIT(1); else CP_WAIT(0);
    __syncthreads();
    FENCE_ASYNC_SHARED();
    if (wid == 0 && elect_one()) { issue_smma(0, 0); TCGEN05_COMMIT(mbs); }

    float rsum = 0.f;
    const int gr = qb * 128 + row;

    for (int kb = 0; kb <= qb; kb++) {
        MBARRIER_WAIT_PARITY(mbs, kb & 1);      // S(kb) ready
        TCGEN05_FENCE_AFTER();
        if (kb < qb) {
            CP_WAIT(0);                          // K(kb+1) landed
            __syncthreads();
            FENCE_ASYNC_SHARED();
            if (wid == 0 && elect_one()) {
                issue_smma((kb + 1) & 1, (kb + 1) & 1);
                TCGEN05_COMMIT(mbs);
            }
        }
        float4 vreg[4];
        const bool havev = (kb + 1 <= qb);
        if (havev) v_ldg(kb + 1, vreg);

        uint32_t s0[32];
        TCGEN05_LD_X32(s0, tmem + (uint32_t)(kb & 1) * 128u + q4 * 32);
        TCGEN05_WAIT_LD();

        if (kb + 2 <= qb) {
            cp_tile(g_K + ((size_t)bh * T_ + (size_t)(kb + 2) * 128) * HD_,
                    FA_KOFF + (uint32_t)(kb & 1) * 32768u);
            CP_COMMIT();
        }

        if (kb > 0) MBARRIER_WAIT_PARITY(mbo, (kb - 1) & 1);

        const int c0 = kb * 128 + q4 * 32;
        if (kb == qb) {
#pragma unroll
            for (int j = 0; j < 32; j++) {
                float p = __expf(__uint_as_float(s0[j]));
                uint32_t u = (c0 + j <= gr) ? f2tf32(p) : 0u;
                rsum += __uint_as_float(u); s0[j] = u;
            }
        } else {
#pragma unroll
            for (int j = 0; j < 32; j++) {
                uint32_t u = f2tf32(__expf(__uint_as_float(s0[j])));
                rsum += __uint_as_float(u); s0[j] = u;
            }
        }
        TCGEN05_ST_X32(tmem + 256 + q4 * 32 + wo, s0);
        if (havev) v_sts((kb + 1) & 1, vreg);
        TCGEN05_WAIT_ST();
        TCGEN05_FENCE_BEFORE();
        FENCE_ASYNC_SHARED();
        __syncthreads();
        if (wid == 0 && elect_one()) {
            TCGEN05_FENCE_AFTER();
            const uint32_t vbase = sb + FA_VOFF + (uint32_t)(kb & 1) * 32768u;
#pragma unroll
            for (int st = 0; st < 16; st++) {
                uint64_t bd = mk_desc(vbase + (st >> 2) * 8192) + (st & 3) * 2;
                mma_tf32_ts(tmem + 384, tmem + 256 + st * 8, bd, IDESC_TF32_N64,
                            (kb > 0) || (st > 0));
            }
            TCGEN05_COMMIT(mbo);
        }
    }

    MBARRIER_WAIT_PARITY(mbo, qb & 1);
    TCGEN05_FENCE_AFTER();

    s_rows[q4][row] = rsum;
    __syncthreads();
    const float inv = 1.f / (s_rows[0][row] + s_rows[1][row] +
                             s_rows[2][row] + s_rows[3][row]);

    if (wid < 8) {
        const int half = wid >> 2;
        uint32_t o0[32];
        TCGEN05_LD_X32(o0, tmem + 384 + half * 32);
        TCGEN05_WAIT_LD();

        const int b = bh >> 4, h = bh & 15;
        const int t = qb * 128 + row;
        float* dst = g_S + ((size_t)(b * T_ + t)) * D_ + h * 64 + half * 32;
#pragma unroll
        for (int j4 = 0; j4 < 8; j4++) {
            float4 o;
            o.x = rnd_tf32(__uint_as_float(o0[j4 * 4 + 0]) * inv);
            o.y = rnd_tf32(__uint_as_float(o0[j4 * 4 + 1]) * inv);
            o.z = rnd_tf32(__uint_as_float(o0[j4 * 4 + 2]) * inv);
            o.w = rnd_tf32(__uint_as_float(o0[j4 * 4 + 3]) * inv);
            *(float4*)&dst[j4 * 4] = o;
        }
    }

    __syncthreads();
    if (wid == 0) TCGEN05_DEALLOC(tmem, 512);

#else  // ------- naive fp32 fallback (non-'a' pass; never selected) ----------
    const int qb = (int)(gridDim.x - 1 - blockIdx.x);
    const int bh = blockIdx.y;
    const int b = bh >> 4, h = bh & 15;
    const int tid = threadIdx.x;
    if (tid < 128) {
        const int t = qb * 128 + tid;
        const float* q = g_Q + ((size_t)bh * T_ + t) * HD_;   // pre-scaled
        float acc[HD_];
        for (int d = 0; d < HD_; d++) acc[d] = 0.f;
        float l = 0.f;
        for (int k = 0; k <= t; k++) {
            const float* kp = g_K + ((size_t)bh * T_ + k) * HD_;
            const float* vp = g_V + ((size_t)bh * T_ + k) * HD_;
            float s = 0.f;
            for (int d = 0; d < HD_; d++) s += q[d] * kp[d];
            float p = expf(s);
            l += p;
            for (int d = 0; d < HD_; d++) acc[d] += p * vp[d];
        }
        for (int d = 0; d < HD_; d++)
            g_S[((size_t)(b * T_ + t)) * D_ + h * 64 + d] = acc[d] / l;
    }
#endif
}

// ---------------------------------------------------------------------------
extern "C" void kernel_launch(void* const* d_in, const int* in_sizes, int n_in,
                              void* d_out, int out_size)
{
    const float* x     = (const float*)d_in[0];
    const float* Wqkv  = (const float*)d_in[1];
    const float* bqkv  = (const float*)d_in[2];
    const float* Wproj = (const float*)d_in[3];
    const float* bproj = (const float*)d_in[4];
    float* out = (float*)d_out;

    const int qkv_smem   = 3 * 65536 + 1024;   // 3 x 64KB stages
    const int proj_smem  = 4 * 49152 + 1024;   // R9-proven 4-stage
    const int flash_smem = FA_DSM + 1024;
    cudaFuncSetAttribute((const void*)tc_gemm_qkv,
                         cudaFuncAttributeMaxDynamicSharedMemorySize, qkv_smem);
    cudaFuncSetAttribute((const void*)tc_gemm_proj,
                         cudaFuncAttributeMaxDynamicSharedMemorySize, proj_smem);
    cudaFuncSetAttribute((const void*)flash_tc,
                         cudaFuncAttributeMaxDynamicSharedMemorySize, flash_smem);

    cvt_tf32_kernel<<<1184, 256>>>(x, Wqkv, Wproj);
    tc_gemm_qkv<<<dim3(3 * D_ / 256, M_ / 256), 256, qkv_smem>>>(bqkv);
    flash_tc<<<dim3(T_ / 128, B_ * H_), FA_THREADS, flash_smem>>>();
    tc_gemm_proj<<<dim3(D_ / 256, M_ / 128), 256, proj_smem>>>(bproj, out);
}

// round 14
// speedup vs baseline: 1.1382x; 1.1382x over previous
#include <cuda_runtime.h>
#include <cstdint>

// Problem constants
#define B_  2
#define T_  2048
#define D_  1024
#define H_  16
#define HD_ 64
#define M_  (B_ * T_)      // 4096

// tcgen05 is sm_103a-SPECIFIC; the harness also compiles a compute_103 pass.
#if defined(__CUDA_ARCH__) && (__CUDA_ARCH__ >= 1000) && defined(__CUDA_ARCH_FEAT_SM103_ALL)
#define HAS_TCGEN05 1
#else
#define HAS_TCGEN05 0
#endif

// Scratch (device globals: allocation-free per harness rules)
__device__ float g_Q[B_ * H_ * T_ * HD_];   // holds Q * 0.125 (exact 2^-3 scale)
__device__ float g_K[B_ * H_ * T_ * HD_];
__device__ float g_V[B_ * H_ * T_ * HD_];
__device__ float g_S[B_ * T_ * D_];
// tf32-pre-rounded copies of the GEMM inputs
__device__ float g_x [M_ * D_];
__device__ float g_W1[3 * D_ * D_];
__device__ float g_W2[D_ * D_];

// ---------------------------------------------------------------------------
// Helpers available on all passes
// ---------------------------------------------------------------------------
__device__ __forceinline__ uint32_t f2tf32(float x) {
    uint32_t u;
    asm("cvt.rna.tf32.f32 %0, %1;" : "=r"(u) : "f"(x));
    return u;
}
__device__ __forceinline__ float rnd_tf32(float x) {
    return __uint_as_float(f2tf32(x));
}
__device__ __forceinline__ uint32_t smem_u32(const void* p) {
    uint32_t a;
    asm("{ .reg .u64 t; cvta.to.shared.u64 t, %1; cvt.u32.u64 %0, t; }"
        : "=r"(a) : "l"(p));
    return a;
}
#define SW128(o) ((o) ^ (((o) >> 3) & 0x70))

#define CP_ASYNC16(dst, src) \
    asm volatile("cp.async.cg.shared.global [%0], [%1], 16;" \
                 :: "r"((uint32_t)(dst)), "l"(src))
#define CP_COMMIT() asm volatile("cp.async.commit_group;" ::: "memory")
#define CP_WAIT(n)  asm volatile("cp.async.wait_group %0;" :: "n"(n) : "memory")

#define MBARRIER_INIT(mb, cnt) \
    asm volatile("mbarrier.init.shared.b64 [%0], %1;" \
                 :: "r"((uint32_t)(mb)), "r"((uint32_t)(cnt)) : "memory")

#define MBARRIER_WAIT_PARITY(mb, par) do {                                        \
    uint32_t _m = (uint32_t)(mb);                                                 \
    uint32_t _p = (uint32_t)(par);                                                \
    uint32_t _done;                                                               \
    asm volatile(                                                                 \
        "{\n\t.reg .pred p;\n\t"                                                  \
        "mbarrier.try_wait.parity.acquire.cta.shared::cta.b64 p, [%1], %2;\n\t"   \
        "selp.b32 %0, 1, 0, p;\n\t}"                                              \
        : "=r"(_done) : "r"(_m), "r"(_p) : "memory");                             \
    if (!_done) {                                                                 \
        asm volatile(                                                             \
            "{\n\t.reg .pred P1;\n\t"                                             \
            "WL_%=:\n\t"                                                          \
            "mbarrier.try_wait.parity.acquire.cta.shared::cta.b64 P1, [%0], %1, 0x989680;\n\t" \
            "@P1 bra.uni WD_%=;\n\t"                                              \
            "bra.uni WL_%=;\n\t"                                                  \
            "WD_%=:\n\t}"                                                         \
            :: "r"(_m), "r"(_p) : "memory");                                      \
    }                                                                             \
} while (0)

#define FENCE_ASYNC_SHARED() asm volatile("fence.proxy.async.shared::cta;" ::: "memory")

#if HAS_TCGEN05
// ---------------------------------------------------------------------------
// tcgen05 helpers (sm_103a only)
// ---------------------------------------------------------------------------
__device__ __forceinline__ uint32_t elect_one() {
    uint32_t p;
    asm volatile("{ .reg .pred p; elect.sync _|p, 0xFFFFFFFF; selp.b32 %0, 1, 0, p; }"
                 : "=r"(p));
    return p;
}
__device__ __forceinline__ uint64_t mk_desc(uint32_t saddr) {
    const uint64_t base = (2ull << 61) | (1ull << 46) | (64ull << 32) | (1ull << 16);
    return base | ((uint64_t)(saddr >> 4) & 0x3FFF);
}

#define IDESC_TF32_N256 ((1u << 4) | (2u << 7) | (2u << 10) | (32u << 17) | (8u << 24))
#define IDESC_TF32_N128 ((1u << 4) | (2u << 7) | (2u << 10) | (16u << 17) | (8u << 24))
#define IDESC_TF32_N64  ((1u << 4) | (2u << 7) | (2u << 10) | ( 8u << 17) | (8u << 24))

__device__ __forceinline__ void mma_tf32_ss(uint32_t d, uint64_t ad, uint64_t bd,
                                            uint32_t idesc, bool en) {
    uint32_t e = en ? 1u : 0u;
    asm volatile(
        "{\n\t.reg .pred p;\n\tsetp.ne.u32 p, %5, 0;\n\t"
        "tcgen05.mma.cta_group::1.kind::tf32 [%0], %1, %2, %3, {%4, %4, %4, %4}, p;\n\t}"
        :: "r"(d), "l"(ad), "l"(bd), "r"(idesc), "r"(0u), "r"(e) : "memory");
}
__device__ __forceinline__ void mma_tf32_ts(uint32_t d, uint32_t a_tm, uint64_t bd,
                                            uint32_t idesc, bool en) {
    uint32_t e = en ? 1u : 0u;
    asm volatile(
        "{\n\t.reg .pred p;\n\tsetp.ne.u32 p, %5, 0;\n\t"
        "tcgen05.mma.cta_group::1.kind::tf32 [%0], [%1], %2, %3, {%4, %4, %4, %4}, p;\n\t}"
        :: "r"(d), "r"(a_tm), "l"(bd), "r"(idesc), "r"(0u), "r"(e) : "memory");
}

#define TCGEN05_ALLOC(smem_res, n) \
    asm volatile("tcgen05.alloc.cta_group::1.sync.aligned.shared::cta.b32 [%0], %1;" \
                 :: "r"((uint32_t)(smem_res)), "r"((uint32_t)(n)) : "memory")
#define TCGEN05_DEALLOC(tm, n) \
    asm volatile("tcgen05.dealloc.cta_group::1.sync.aligned.b32 %0, %1;" \
                 :: "r"(tm), "r"((uint32_t)(n)))
#define TCGEN05_RELINQ() \
    asm volatile("tcgen05.relinquish_alloc_permit.cta_group::1.sync.aligned;")
#define TCGEN05_COMMIT(mb) \
    asm volatile("tcgen05.commit.cta_group::1.mbarrier::arrive::one.shared::cluster.b64 [%0];" \
                 :: "r"((uint32_t)(mb)) : "memory")
#define TCGEN05_FENCE_BEFORE() asm volatile("tcgen05.fence::before_thread_sync;" ::: "memory")
#define TCGEN05_FENCE_AFTER()  asm volatile("tcgen05.fence::after_thread_sync;" ::: "memory")
#define TCGEN05_WAIT_LD() asm volatile("tcgen05.wait::ld.sync.aligned;" ::: "memory")
#define TCGEN05_WAIT_ST() asm volatile("tcgen05.wait::st.sync.aligned;" ::: "memory")

#define TCGEN05_LD_X32(r, ta) \
    asm volatile( \
        "tcgen05.ld.sync.aligned.32x32b.x32.b32 " \
        "{%0, %1, %2, %3, %4, %5, %6, %7, %8, %9, %10, %11, %12, %13, %14, %15, " \
        " %16, %17, %18, %19, %20, %21, %22, %23, %24, %25, %26, %27, %28, %29, %30, %31}, [%32];" \
        : "=r"((r)[0]),  "=r"((r)[1]),  "=r"((r)[2]),  "=r"((r)[3]), \
          "=r"((r)[4]),  "=r"((r)[5]),  "=r"((r)[6]),  "=r"((r)[7]), \
          "=r"((r)[8]),  "=r"((r)[9]),  "=r"((r)[10]), "=r"((r)[11]), \
          "=r"((r)[12]), "=r"((r)[13]), "=r"((r)[14]), "=r"((r)[15]), \
          "=r"((r)[16]), "=r"((r)[17]), "=r"((r)[18]), "=r"((r)[19]), \
          "=r"((r)[20]), "=r"((r)[21]), "=r"((r)[22]), "=r"((r)[23]), \
          "=r"((r)[24]), "=r"((r)[25]), "=r"((r)[26]), "=r"((r)[27]), \
          "=r"((r)[28]), "=r"((r)[29]), "=r"((r)[30]), "=r"((r)[31]) \
        : "r"(ta))

#define TCGEN05_LD_X16(r, ta) \
    asm volatile( \
        "tcgen05.ld.sync.aligned.32x32b.x16.b32 " \
        "{%0, %1, %2, %3, %4, %5, %6, %7, %8, %9, %10, %11, %12, %13, %14, %15}, [%16];" \
        : "=r"((r)[0]),  "=r"((r)[1]),  "=r"((r)[2]),  "=r"((r)[3]), \
          "=r"((r)[4]),  "=r"((r)[5]),  "=r"((r)[6]),  "=r"((r)[7]), \
          "=r"((r)[8]),  "=r"((r)[9]),  "=r"((r)[10]), "=r"((r)[11]), \
          "=r"((r)[12]), "=r"((r)[13]), "=r"((r)[14]), "=r"((r)[15]) \
        : "r"(ta))

#define TCGEN05_ST_X32(ta, r) \
    asm volatile( \
        "tcgen05.st.sync.aligned.32x32b.x32.b32 [%0], " \
        "{%1, %2, %3, %4, %5, %6, %7, %8, %9, %10, %11, %12, %13, %14, %15, %16, " \
        " %17, %18, %19, %20, %21, %22, %23, %24, %25, %26, %27, %28, %29, %30, %31, %32};" \
        :: "r"(ta), \
           "r"((r)[0]),  "r"((r)[1]),  "r"((r)[2]),  "r"((r)[3]), \
           "r"((r)[4]),  "r"((r)[5]),  "r"((r)[6]),  "r"((r)[7]), \
           "r"((r)[8]),  "r"((r)[9]),  "r"((r)[10]), "r"((r)[11]), \
           "r"((r)[12]), "r"((r)[13]), "r"((r)[14]), "r"((r)[15]), \
           "r"((r)[16]), "r"((r)[17]), "r"((r)[18]), "r"((r)[19]), \
           "r"((r)[20]), "r"((r)[21]), "r"((r)[22]), "r"((r)[23]), \
           "r"((r)[24]), "r"((r)[25]), "r"((r)[26]), "r"((r)[27]), \
           "r"((r)[28]), "r"((r)[29]), "r"((r)[30]), "r"((r)[31]) \
        : "memory")

#define TCGEN05_ST_X16(ta, r) \
    asm volatile( \
        "tcgen05.st.sync.aligned.32x32b.x16.b32 [%0], " \
        "{%1, %2, %3, %4, %5, %6, %7, %8, %9, %10, %11, %12, %13, %14, %15, %16};" \
        :: "r"(ta), \
           "r"((r)[0]),  "r"((r)[1]),  "r"((r)[2]),  "r"((r)[3]), \
           "r"((r)[4]),  "r"((r)[5]),  "r"((r)[6]),  "r"((r)[7]), \
           "r"((r)[8]),  "r"((r)[9]),  "r"((r)[10]), "r"((r)[11]), \
           "r"((r)[12]), "r"((r)[13]), "r"((r)[14]), "r"((r)[15]) \
        : "memory")
#endif  // HAS_TCGEN05

// ---------------------------------------------------------------------------
// Kernel 0: pre-round x, Wqkv, Wproj to tf32 (rna) into device-global copies.
// ---------------------------------------------------------------------------
#define NX4  1048576
#define NW14  786432
#define NW24  262144
#define NTOT (NX4 + NW14 + NW24)

__global__ void cvt_tf32_kernel(const float* __restrict__ x,
                                const float* __restrict__ w1,
                                const float* __restrict__ w2)
{
    const int stride = gridDim.x * blockDim.x;
    for (int i = blockIdx.x * blockDim.x + threadIdx.x; i < NTOT; i += stride) {
        const float4* s; float4* d; int off;
        if (i < NX4)              { s = (const float4*)x;  d = (float4*)g_x;  off = i; }
        else if (i < NX4 + NW14)  { s = (const float4*)w1; d = (float4*)g_W1; off = i - NX4; }
        else                      { s = (const float4*)w2; d = (float4*)g_W2; off = i - NX4 - NW14; }
        float4 v = s[off];
        v.x = rnd_tf32(v.x); v.y = rnd_tf32(v.y);
        v.z = rnd_tf32(v.z); v.w = rnd_tf32(v.w);
        d[off] = v;
    }
}

// ---------------------------------------------------------------------------
// GEMM (exact R9 config): C[128m x 256n] per CTA, 4-stage cp.async pipeline,
// stage-reuse distance 2, depth-3 prefetch. EPI==1: QKV scatter; EPI==0: out.
// ---------------------------------------------------------------------------
#define GST 49152u

template <int EPI>
__global__ __launch_bounds__(256)
void tc_gemm(const float* __restrict__ bias, float* __restrict__ out)
{
#if HAS_TCGEN05
    extern __shared__ uint8_t dsm_raw[];
    uint8_t* dsm = (uint8_t*)((((uintptr_t)dsm_raw) + 1023) & ~(uintptr_t)1023);

    __shared__ uint32_t s_tmem;
    __shared__ __align__(8) unsigned long long s_mbar[4];

    const int tid  = threadIdx.x;
    const int wid  = tid >> 5;
    const int lane = tid & 31;
    const int m0 = blockIdx.y * 128, n0 = blockIdx.x * 256;
    const uint32_t sb = smem_u32(dsm);

    if (wid == 0) TCGEN05_ALLOC(smem_u32(&s_tmem), 256);
    if (tid == 0)
#pragma unroll
        for (int j = 0; j < 4; j++) MBARRIER_INIT(smem_u32(&s_mbar[j]), 1);
    __syncthreads();
    const uint32_t tmem = s_tmem;
    uint32_t mb[4];
#pragma unroll
    for (int j = 0; j < 4; j++) mb[j] = smem_u32(&s_mbar[j]);

    const float* Abase = (EPI == 1) ? g_x  : g_S;
    const float* Wbase = (EPI == 1) ? g_W1 : g_W2;

    const int row = tid >> 3;
    const int q   = tid & 7;
    const char* Ag = (const char*)(Abase + (size_t)(m0 + row) * 1024 + q * 4);
    const char* Wg = (const char*)(Wbase + (size_t)(n0 + row) * 1024 + q * 4);

    const uint32_t doff = SW128((uint32_t)row * 128u + (uint32_t)q * 16u);
    // SW128 permutes only bits [6:4]^[9:7]; +i*4096 (bit 12+) commutes with it.

    auto issue_stage = [&](int kt, int st) {
        const uint32_t base = sb + (uint32_t)st * GST;
        const char* a = Ag + (size_t)kt * 128;
        const char* w = Wg + (size_t)kt * 128;
#pragma unroll
        for (int i = 0; i < 4; i++)
            CP_ASYNC16(base + ((doff + 4096u * i) & 0x7FFFu), a + (size_t)i * 131072);
#pragma unroll
        for (int i = 0; i < 8; i++)
            CP_ASYNC16(base + 16384u + ((doff + 4096u * i) & 0xFFFFu), w + (size_t)i * 131072);
    };

    issue_stage(0, 0); CP_COMMIT();
    issue_stage(1, 1); CP_COMMIT();

    for (int kt = 0; kt < 32; kt++) {
        if (kt + 2 < 32) {
            if (kt >= 2)
                MBARRIER_WAIT_PARITY(mb[(kt - 2) & 3], ((kt - 2) >> 2) & 1);
            issue_stage(kt + 2, (kt + 2) & 3); CP_COMMIT();
            CP_WAIT(2);          // stage kt landed, 3 groups deep
        } else if (kt == 30) {
            CP_WAIT(1);
        } else {
            CP_WAIT(0);
        }
        __syncthreads();
        FENCE_ASYNC_SHARED();
        if (wid == 0 && elect_one()) {
            const uint32_t base = sb + (uint32_t)(kt & 3) * GST;
            uint64_t ad = mk_desc(base), bd = mk_desc(base + 16384u);
#pragma unroll
            for (int s = 0; s < 4; s++)
                mma_tf32_ss(tmem, ad + s * 2, bd + s * 2, IDESC_TF32_N256,
                            (kt > 0) || (s > 0));
            TCGEN05_COMMIT(mb[kt & 3]);
        }
    }
#pragma unroll
    for (int j = 0; j < 4; j++) MBARRIER_WAIT_PARITY(mb[j], 1);
    TCGEN05_FENCE_AFTER();

    // Epilogue: TMEM -> smem transpose (pad 33) -> coalesced global
    float* dch = (float*)dsm;
    for (int c = 0; c < 8; c++) {
        __syncthreads();
        if (wid < 4) {
            uint32_t r[32];
            TCGEN05_LD_X32(r, tmem + c * 32);
            TCGEN05_WAIT_LD();
            const int rr = wid * 32 + lane;
#pragma unroll
            for (int j = 0; j < 32; j++) dch[rr * 33 + j] = __uint_as_float(r[j]);
        }
        __syncthreads();
#pragma unroll
        for (int i = 0; i < 4; i++) {
            const int rr = (tid >> 3) + 32 * i;
            const int qq = tid & 7;
            const int n  = n0 + c * 32 + qq * 4;
            float4 bb = *(const float4*)&bias[n];
            float4 o;
            o.x = dch[rr * 33 + qq * 4 + 0] + bb.x;
            o.y = dch[rr * 33 + qq * 4 + 1] + bb.y;
            o.z = dch[rr * 33 + qq * 4 + 2] + bb.z;
            o.w = dch[rr * 33 + qq * 4 + 3] + bb.w;
            const int m = m0 + rr;
            if (EPI == 1) {
                const int which = n >> 10;
                // fold softmax scale into Q: *2^-3 is mantissa-exact
                const float sc = (which == 0) ? 0.125f : 1.0f;
                o.x = rnd_tf32(o.x * sc); o.y = rnd_tf32(o.y * sc);
                o.z = rnd_tf32(o.z * sc); o.w = rnd_tf32(o.w * sc);
                const int b = m >> 11, t = m & 2047;
                const int dn = n & 1023, h = dn >> 6, hd = dn & 63;
                float* dst = (which == 0) ? g_Q : ((which == 1) ? g_K : g_V);
                *(float4*)&dst[((size_t)(b * H_ + h) * T_ + t) * HD_ + hd] = o;
            } else {
                *(float4*)&out[(size_t)m * D_ + n] = o;
            }
        }
    }
    __syncthreads();
    if (wid == 0) { TCGEN05_RELINQ(); TCGEN05_DEALLOC(tmem, 256); }

#else  // ------- naive fallback (non-'a' compile pass; never selected) -------
    const int tid = threadIdx.x;
    const int m0 = blockIdx.y * 128, n0 = blockIdx.x * 256;
    const float* Abase = (EPI == 1) ? g_x : g_S;
    const float* Wbase = (EPI == 1) ? g_W1 : g_W2;
    for (int idx = tid; idx < 128 * 256; idx += 256) {
        int m = m0 + (idx >> 8);
        int n = n0 + (idx & 255);
        float acc = bias[n];
        for (int k = 0; k < 1024; k++)
            acc += Abase[(size_t)m * 1024 + k] * Wbase[(size_t)n * 1024 + k];
        if (EPI == 1) {
            int b = m >> 11, t = m & 2047;
            int which = n >> 10, dn = n & 1023, h = dn >> 6, hd = dn & 63;
            if (which == 0) acc *= 0.125f;
            float* dst = (which == 0) ? g_Q : ((which == 1) ? g_K : g_V);
            dst[((size_t)(b * H_ + h) * T_ + t) * HD_ + hd] = acc;
        } else {
            out[(size_t)m * D_ + n] = acc;
        }
    }
#endif
}

// ---------------------------------------------------------------------------
// tcgen05 causal flash attention (R9 config, one change: LDTM split into two
// x16 halves with the second half's latency hidden under exp of the first).
// BR=BC=128, HD=64, grid (16, 32), 512 thr; warp (w&3, w>>2) owns 32 S cols.
// TMEM: S0@0, S1@128, P@256, O@384. Q pre-scaled by 0.125.
// ---------------------------------------------------------------------------
#define FA_QOFF 0u
#define FA_KOFF 32768u
#define FA_VOFF 98304u
#define FA_DSM  163840
#define FA_THREADS 512

__global__ __launch_bounds__(FA_THREADS)
void flash_tc()
{
#if HAS_TCGEN05
    extern __shared__ uint8_t dsm_raw[];
    uint8_t* dsm = (uint8_t*)((((uintptr_t)dsm_raw) + 1023) & ~(uintptr_t)1023);

    __shared__ uint32_t s_tmem;
    __shared__ __align__(8) unsigned long long s_mbar_s, s_mbar_o;
    __shared__ float s_rows[4][128];

    const int tid  = threadIdx.x;
    const int wid  = tid >> 5;
    const int lane = tid & 31;
    const int qb   = (int)(gridDim.x - 1 - blockIdx.x);   // heavy tiles first
    const int bh   = blockIdx.y;

    const int rg  = wid & 3;
    const int q4  = wid >> 2;
    const int row = (rg << 5) + lane;
    const uint32_t wo = (uint32_t)rg << 21;

    const uint32_t sb = smem_u32(dsm);
    if (wid == 0) TCGEN05_ALLOC(smem_u32(&s_tmem), 512);
    if (tid == 0) { MBARRIER_INIT(smem_u32(&s_mbar_s), 1); MBARRIER_INIT(smem_u32(&s_mbar_o), 1); }
    __syncthreads();
    const uint32_t tmem = s_tmem;
    const uint32_t mbs = smem_u32(&s_mbar_s), mbo = smem_u32(&s_mbar_o);

    const int lr0 = tid >> 4;
    const int ld4 = (tid & 15) << 2;
    const int lcj = ld4 >> 5, lkk = ld4 & 31;
    const uint32_t ldst = (uint32_t)lcj * 16384u + SW128((uint32_t)lr0 * 128u + (uint32_t)lkk * 4u);

    auto cp_tile = [&](const float* Gg, uint32_t smoff) {
#pragma unroll
        for (int it = 0; it < 4; it++)
            CP_ASYNC16(sb + smoff + ((ldst + 4096u * it) & 0x7FFFu),
                       (const char*)(Gg + (size_t)(lr0 + 32 * it) * 64 + ld4));
    };

    const float* Qg = g_Q + ((size_t)bh * T_ + (size_t)qb * 128) * HD_;

    const int vrb = tid >> 4, vdb = tid & 15;

    auto issue_smma = [&](int kbuf, int sbuf) {
        const uint32_t kbase = sb + FA_KOFF + (uint32_t)kbuf * 32768u;
#pragma unroll
        for (int cj = 0; cj < 2; cj++) {
            uint64_t ad = mk_desc(sb + FA_QOFF + cj * 16384);
            uint64_t bd = mk_desc(kbase + cj * 16384);
#pragma unroll
            for (int s = 0; s < 4; s++)
                mma_tf32_ss(tmem + sbuf * 128, ad + s * 2, bd + s * 2,
                            IDESC_TF32_N128, (cj > 0) || (s > 0));
        }
    };

    auto v_ldg = [&](int kb, float4* vreg) {
        const float* Vg = g_V + ((size_t)bh * T_ + (size_t)kb * 128) * HD_;
        const int r0 = vrb * 4, d0 = vdb * 4;
#pragma unroll
        for (int m = 0; m < 4; m++)
            vreg[m] = *(const float4*)&Vg[(r0 + m) * 64 + d0];
    };
    auto v_sts = [&](int b, const float4* vreg) {
        const uint32_t vbase = FA_VOFF + (uint32_t)b * 32768u;
        const int r0 = vrb * 4, d0 = vdb * 4;
        const int vj = r0 >> 5, kk0 = r0 & 31;
#pragma unroll
        for (int m = 0; m < 4; m++) {
            float4 u;
            u.x = ((const float*)&vreg[0])[m];
            u.y = ((const float*)&vreg[1])[m];
            u.z = ((const float*)&vreg[2])[m];
            u.w = ((const float*)&vreg[3])[m];
            uint32_t off = (uint32_t)(d0 + m) * 128u + (uint32_t)kk0 * 4u;
            *(float4*)(dsm + vbase + vj * 8192 + SW128(off)) = u;
        }
    };

    // ---- prologue ----
    cp_tile(Qg, FA_QOFF);
    cp_tile(g_K + ((size_t)bh * T_ + 0) * HD_, FA_KOFF);
    CP_COMMIT();
    if (qb > 0) {
        cp_tile(g_K + ((size_t)bh * T_ + 128) * HD_, FA_KOFF + 32768u);
        CP_COMMIT();
    }
    {
        float4 v0[4];
        v_ldg(0, v0);
        v_sts(0, v0);
    }
    if (qb > 0) CP_WAIT(1); else CP_WAIT(0);
    __syncthreads();
    FENCE_ASYNC_SHARED();
    if (wid == 0 && elect_one()) { issue_smma(0, 0); TCGEN05_COMMIT(mbs); }

    float rsum = 0.f;
    const int gr = qb * 128 + row;

    for (int kb = 0; kb <= qb; kb++) {
        MBARRIER_WAIT_PARITY(mbs, kb & 1);      // S(kb) ready
        TCGEN05_FENCE_AFTER();
        if (kb < qb) {
            CP_WAIT(0);                          // K(kb+1) landed
            __syncthreads();
            FENCE_ASYNC_SHARED();
            if (wid == 0 && elect_one()) {
                issue_smma((kb + 1) & 1, (kb + 1) & 1);
                TCGEN05_COMMIT(mbs);
            }
        }
        float4 vreg[4];
        const bool havev = (kb + 1 <= qb);
        if (havev) v_ldg(kb + 1, vreg);

        // --- split LDTM: half 0, wait; half 1 in flight under exp(half 0) ---
        uint32_t s0[16], s1[16];
        const uint32_t sbase = tmem + (uint32_t)(kb & 1) * 128u + q4 * 32;
        TCGEN05_LD_X16(s0, sbase);
        TCGEN05_WAIT_LD();
        TCGEN05_LD_X16(s1, sbase + 16);          // in flight during exp(s0)

        if (kb + 2 <= qb) {
            cp_tile(g_K + ((size_t)bh * T_ + (size_t)(kb + 2) * 128) * HD_,
                    FA_KOFF + (uint32_t)(kb & 1) * 32768u);
            CP_COMMIT();
        }

        if (kb > 0) MBARRIER_WAIT_PARITY(mbo, (kb - 1) & 1);

        const int c0 = kb * 128 + q4 * 32;
        if (kb == qb) {
#pragma unroll
            for (int j = 0; j < 16; j++) {
                float p = __expf(__uint_as_float(s0[j]));
                uint32_t u = (c0 + j <= gr) ? f2tf32(p) : 0u;
                rsum += __uint_as_float(u); s0[j] = u;
            }
            TCGEN05_WAIT_LD();
#pragma unroll
            for (int j = 0; j < 16; j++) {
                float p = __expf(__uint_as_float(s1[j]));
                uint32_t u = (c0 + 16 + j <= gr) ? f2tf32(p) : 0u;
                rsum += __uint_as_float(u); s1[j] = u;
            }
        } else {
#pragma unroll
            for (int j = 0; j < 16; j++) {
                uint32_t u = f2tf32(__expf(__uint_as_float(s0[j])));
                rsum += __uint_as_float(u); s0[j] = u;
            }
            TCGEN05_WAIT_LD();
#pragma unroll
            for (int j = 0; j < 16; j++) {
                uint32_t u = f2tf32(__expf(__uint_as_float(s1[j])));
                rsum += __uint_as_float(u); s1[j] = u;
            }
        }
        TCGEN05_ST_X16(tmem + 256 + q4 * 32 + wo, s0);
        TCGEN05_ST_X16(tmem + 256 + q4 * 32 + 16 + wo, s1);
        if (havev) v_sts((kb + 1) & 1, vreg);
        TCGEN05_WAIT_ST();
        TCGEN05_FENCE_BEFORE();
        FENCE_ASYNC_SHARED();
        __syncthreads();
        if (wid == 0 && elect_one()) {
            TCGEN05_FENCE_AFTER();
            const uint32_t vbase = sb + FA_VOFF + (uint32_t)(kb & 1) * 32768u;
#pragma unroll
            for (int st = 0; st < 16; st++) {
                uint64_t bd = mk_desc(vbase + (st >> 2) * 8192) + (st & 3) * 2;
                mma_tf32_ts(tmem + 384, tmem + 256 + st * 8, bd, IDESC_TF32_N64,
                            (kb > 0) || (st > 0));
            }
            TCGEN05_COMMIT(mbo);
        }
    }

    MBARRIER_WAIT_PARITY(mbo, qb & 1);
    TCGEN05_FENCE_AFTER();

    s_rows[q4][row] = rsum;
    __syncthreads();
    const float inv = 1.f / (s_rows[0][row] + s_rows[1][row] +
                             s_rows[2][row] + s_rows[3][row]);

    if (wid < 8) {
        const int half = wid >> 2;
        uint32_t o0[32];
        TCGEN05_LD_X32(o0, tmem + 384 + half * 32);
        TCGEN05_WAIT_LD();

        const int b = bh >> 4, h = bh & 15;
        const int t = qb * 128 + row;
        float* dst = g_S + ((size_t)(b * T_ + t)) * D_ + h * 64 + half * 32;
#pragma unroll
        for (int j4 = 0; j4 < 8; j4++) {
            float4 o;
            o.x = rnd_tf32(__uint_as_float(o0[j4 * 4 + 0]) * inv);
            o.y = rnd_tf32(__uint_as_float(o0[j4 * 4 + 1]) * inv);
            o.z = rnd_tf32(__uint_as_float(o0[j4 * 4 + 2]) * inv);
            o.w = rnd_tf32(__uint_as_float(o0[j4 * 4 + 3]) * inv);
            *(float4*)&dst[j4 * 4] = o;
        }
    }

    __syncthreads();
    if (wid == 0) { TCGEN05_RELINQ(); TCGEN05_DEALLOC(tmem, 512); }

#else  // ------- naive fp32 fallback (non-'a' pass; never selected) ----------
    const int qb = (int)(gridDim.x - 1 - blockIdx.x);
    const int bh = blockIdx.y;
    const int b = bh >> 4, h = bh & 15;
    const int tid = threadIdx.x;
    if (tid < 128) {
        const int t = qb * 128 + tid;
        const float* q = g_Q + ((size_t)bh * T_ + t) * HD_;   // pre-scaled
        float acc[HD_];
        for (int d = 0; d < HD_; d++) acc[d] = 0.f;
        float l = 0.f;
        for (int k = 0; k <= t; k++) {
            const float* kp = g_K + ((size_t)bh * T_ + k) * HD_;
            const float* vp = g_V + ((size_t)bh * T_ + k) * HD_;
            float s = 0.f;
            for (int d = 0; d < HD_; d++) s += q[d] * kp[d];
            float p = expf(s);
            l += p;
            for (int d = 0; d < HD_; d++) acc[d] += p * vp[d];
        }
        for (int d = 0; d < HD_; d++)
            g_S[((size_t)(b * T_ + t)) * D_ + h * 64 + d] = acc[d] / l;
    }
#endif
}

// ---------------------------------------------------------------------------
extern "C" void kernel_launch(void* const* d_in, const int* in_sizes, int n_in,
                              void* d_out, int out_size)
{
    const float* x     = (const float*)d_in[0];
    const float* Wqkv  = (const float*)d_in[1];
    const float* bqkv  = (const float*)d_in[2];
    const float* Wproj = (const float*)d_in[3];
    const float* bproj = (const float*)d_in[4];
    float* out = (float*)d_out;

    const int gemm_smem  = 4 * 49152 + 1024;   // R9-proven 4-stage
    const int flash_smem = FA_DSM + 1024;
    cudaFuncSetAttribute((const void*)tc_gemm<1>,
                         cudaFuncAttributeMaxDynamicSharedMemorySize, gemm_smem);
    cudaFuncSetAttribute((const void*)tc_gemm<0>,
                         cudaFuncAttributeMaxDynamicSharedMemorySize, gemm_smem);
    cudaFuncSetAttribute((const void*)flash_tc,
                         cudaFuncAttributeMaxDynamicSharedMemorySize, flash_smem);

    cvt_tf32_kernel<<<1184, 256>>>(x, Wqkv, Wproj);
    tc_gemm<1><<<dim3(3 * D_ / 256, M_ / 128), 256, gemm_smem>>>(bqkv, nullptr);
    flash_tc<<<dim3(T_ / 128, B_ * H_), FA_THREADS, flash_smem>>>();
    tc_gemm<0><<<dim3(D_ / 256, M_ / 128), 256, gemm_smem>>>(bproj, out);
}